// round 9
// baseline (speedup 1.0000x reference)
#include <cuda_runtime.h>

// Problem constants
#define BATCH 8
#define HW    256
#define HW2   65536
#define CMID  64
#define C3    169
#define KF    13
#define HO    244
#define HO2   59536   // 244*244

typedef unsigned long long u64;

// packed f32x2 helpers (sm_103a dual-lane fp32 FMA)
__device__ __forceinline__ u64 packdup(float x) {
    u64 r; asm("mov.b64 %0, {%1, %1};" : "=l"(r) : "f"(x)); return r;
}
__device__ __forceinline__ u64 pack2(float x, float y) {
    u64 r; asm("mov.b64 %0, {%1, %2};" : "=l"(r) : "f"(x), "f"(y)); return r;
}
__device__ __forceinline__ void fma2(u64& d, u64 a, u64 b) {
    asm("fma.rn.f32x2 %0, %1, %2, %0;" : "+l"(d) : "l"(a), "l"(b));
}
__device__ __forceinline__ float2 unpk(u64 v) {
    float2 r; asm("mov.b64 {%0, %1}, %2;" : "=f"(r.x), "=f"(r.y) : "l"(v)); return r;
}

// Scratch (device globals; no allocation in kernel_launch)
__device__ float g_h1[BATCH * CMID * HW2];   // conv1 out (relu)
__device__ float g_h2[BATCH * CMID * HW2];   // conv2 out (relu)
__device__ float g_w [BATCH * C3 * HO2];     // conv3 out, cropped to interior
__device__ float g_W2t[CMID * 9 * CMID];     // [(ci*9+uv)*64 + co]
__device__ float g_W3t[CMID * 9 * C3];       // [(ci*9+uv)*169 + co]

// ---------------------------------------------------------------------------
// K0: weight transposes so the shared-memory weight tiles load coalesced
// ---------------------------------------------------------------------------
__global__ void transpose_w2(const float* __restrict__ W2) {
    int idx = blockIdx.x * 256 + threadIdx.x;
    if (idx < CMID * CMID * 9) {
        int co = idx / 576;        // W2[co][ci][u][v]
        int r  = idx % 576;        // ci*9 + uv
        g_W2t[r * CMID + co] = W2[idx];
    }
}

__global__ void transpose_w3(const float* __restrict__ W3) {
    int idx = blockIdx.x * 256 + threadIdx.x;
    if (idx < C3 * CMID * 9) {
        int co = idx / 576;
        int r  = idx % 576;
        g_W3t[r * C3 + co] = W3[idx];
    }
}

// ---------------------------------------------------------------------------
// K1: conv1 (1 -> 64) + relu, SAME. Tile 32x8, 256 threads, 1 px/thread.
// ---------------------------------------------------------------------------
__global__ __launch_bounds__(256) void conv1_kernel(
    const float* __restrict__ x, const float* __restrict__ W1,
    const float* __restrict__ b1)
{
    __shared__ float sW[576];
    __shared__ float sB[64];
    __shared__ float sX[10][35];

    int b  = blockIdx.z;
    int x0 = blockIdx.x * 32;
    int y0 = blockIdx.y * 8;
    int tid = threadIdx.x;

    for (int e = tid; e < 576; e += 256) sW[e] = W1[e];
    if (tid < 64) sB[tid] = b1[tid];
    for (int e = tid; e < 340; e += 256) {
        int r = e / 34, cc = e % 34;
        int gr = y0 - 1 + r, gc = x0 - 1 + cc;
        float v = 0.f;
        if (gr >= 0 && gr < HW && gc >= 0 && gc < HW)
            v = x[b * HW2 + gr * HW + gc];
        sX[r][cc] = v;
    }
    __syncthreads();

    int tx = tid & 31, ty = tid >> 5;
    float xv[9];
#pragma unroll
    for (int u = 0; u < 3; u++)
#pragma unroll
        for (int v = 0; v < 3; v++) xv[u * 3 + v] = sX[ty + u][tx + v];

    int oidx = (b * CMID) * HW2 + (y0 + ty) * HW + (x0 + tx);
#pragma unroll 4
    for (int co = 0; co < CMID; co++) {
        float a = sB[co];
#pragma unroll
        for (int k = 0; k < 9; k++) a += xv[k] * sW[co * 9 + k];
        g_h1[oidx + co * HW2] = fmaxf(a, 0.f);
    }
}

// ---------------------------------------------------------------------------
// K2: conv2 (64 -> 64) + relu, SAME, packed f32x2.
// 256 threads = 32 px-slots (8 rows x 4 groups-of-4px) x 8 co-groups.
// Each thread: 4 px x 8 co as 4x4 packed accumulators (lanes = co pair).
// ---------------------------------------------------------------------------
#define TW  16
#define TH  8
#define CIC 8
#define SROW 20   // sIn row stride (floats), keeps px0*4B 16B-aligned

__global__ __launch_bounds__(256, 3) void conv2_kernel(const float* __restrict__ b2)
{
    __shared__ float sIn[CIC][TH + 2][SROW];
    __shared__ __align__(16) float sW[CIC][9][CMID];

    int b  = blockIdx.z;
    int x0 = blockIdx.x * TW;
    int y0 = blockIdx.y * TH;
    int tid  = threadIdx.x;
    int cg   = tid >> 5;        // 0..7 co-group (one warp per cg)
    int slot = tid & 31;
    int sy   = slot >> 2;       // 0..7 row
    int sx   = slot & 3;        // 0..3
    int px0  = sx * 4;
    int co0  = cg * 8;

    u64 acc[4][4];
#pragma unroll
    for (int cp = 0; cp < 4; cp++) {
        u64 bb = pack2(__ldg(&b2[co0 + 2 * cp]), __ldg(&b2[co0 + 2 * cp + 1]));
#pragma unroll
        for (int k = 0; k < 4; k++) acc[k][cp] = bb;
    }

#pragma unroll 1
    for (int cic = 0; cic < CMID / CIC; cic++) {
        int ci0 = cic * CIC;
        __syncthreads();
        // input tile chunk (zero pad at borders); cols 0..17 used
        for (int e = tid; e < CIC * (TH + 2) * 18; e += 256) {
            int ci  = e / 180;
            int rem = e % 180;
            int r = rem / 18, cc = rem % 18;
            int gr = y0 - 1 + r, gc = x0 - 1 + cc;
            float v = 0.f;
            if (gr >= 0 && gr < HW && gc >= 0 && gc < HW)
                v = g_h1[(b * CMID + ci0 + ci) * HW2 + gr * HW + gc];
            sIn[ci][r][cc] = v;
        }
        // weight chunk (coalesced)
        for (int e = tid; e < CIC * 9 * CMID; e += 256) {
            int co = e & 63;
            int rc = e >> 6;
            int ci = rc / 9, uv = rc % 9;
            sW[ci][uv][co] = g_W2t[((ci0 + ci) * 9 + uv) * CMID + co];
        }
        __syncthreads();

#pragma unroll 1
        for (int ci = 0; ci < CIC; ci++) {
#pragma unroll
            for (int u = 0; u < 3; u++) {
                const float4 xa = *(const float4*)&sIn[ci][sy + u][px0];
                const float2 xb = *(const float2*)&sIn[ci][sy + u][px0 + 4];
                u64 xp[6];
                xp[0] = packdup(xa.x); xp[1] = packdup(xa.y);
                xp[2] = packdup(xa.z); xp[3] = packdup(xa.w);
                xp[4] = packdup(xb.x); xp[5] = packdup(xb.y);
#pragma unroll
                for (int v = 0; v < 3; v++) {
                    const ulonglong2 wA = *(const ulonglong2*)&sW[ci][u * 3 + v][co0];
                    const ulonglong2 wB = *(const ulonglong2*)&sW[ci][u * 3 + v][co0 + 4];
#pragma unroll
                    for (int k = 0; k < 4; k++) {
                        u64 xk = xp[k + v];
                        fma2(acc[k][0], xk, wA.x);
                        fma2(acc[k][1], xk, wA.y);
                        fma2(acc[k][2], xk, wB.x);
                        fma2(acc[k][3], xk, wB.y);
                    }
                }
            }
        }
    }

#pragma unroll
    for (int cp = 0; cp < 4; cp++) {
        float2 p0 = unpk(acc[0][cp]), p1 = unpk(acc[1][cp]);
        float2 p2 = unpk(acc[2][cp]), p3 = unpk(acc[3][cp]);
        float4 e0 = make_float4(fmaxf(p0.x, 0.f), fmaxf(p1.x, 0.f),
                                fmaxf(p2.x, 0.f), fmaxf(p3.x, 0.f));
        float4 e1 = make_float4(fmaxf(p0.y, 0.f), fmaxf(p1.y, 0.f),
                                fmaxf(p2.y, 0.f), fmaxf(p3.y, 0.f));
        int base = (y0 + sy) * HW + x0 + px0;
        *(float4*)&g_h2[(b * CMID + co0 + 2 * cp)     * HW2 + base] = e0;
        *(float4*)&g_h2[(b * CMID + co0 + 2 * cp + 1) * HW2 + base] = e1;
    }
}

// ---------------------------------------------------------------------------
// K3: conv3 (64 -> 169) on the cropped interior only, packed f32x2.
// Output (i,j) in [0,244)^2 = conv3 at (i+6, j+6). 3 co-passes of 64.
// ---------------------------------------------------------------------------
__global__ __launch_bounds__(256, 3) void conv3_kernel(const float* __restrict__ b3)
{
    __shared__ float sIn[CIC][TH + 2][SROW];
    __shared__ __align__(16) float sW[CIC][9][CMID];

    int b  = blockIdx.z;
    int j0 = blockIdx.x * TW;
    int i0 = blockIdx.y * TH;
    int tid  = threadIdx.x;
    int cg   = tid >> 5;
    int slot = tid & 31;
    int sy   = slot >> 2;
    int sx   = slot & 3;
    int px0  = sx * 4;
    int co0  = cg * 8;

#pragma unroll 1
    for (int coit = 0; coit < 3; coit++) {
        int cobase = coit * 64 + co0;

        u64 acc[4][4];
#pragma unroll
        for (int cp = 0; cp < 4; cp++) {
            int c0 = cobase + 2 * cp, c1 = cobase + 2 * cp + 1;
            u64 bb = pack2(c0 < C3 ? __ldg(&b3[c0]) : 0.f,
                           c1 < C3 ? __ldg(&b3[c1]) : 0.f);
#pragma unroll
            for (int k = 0; k < 4; k++) acc[k][cp] = bb;
        }

#pragma unroll 1
        for (int cic = 0; cic < CMID / CIC; cic++) {
            int ci0 = cic * CIC;
            __syncthreads();
            for (int e = tid; e < CIC * (TH + 2) * 18; e += 256) {
                int ci  = e / 180;
                int rem = e % 180;
                int r = rem / 18, cc = rem % 18;
                int gr = i0 + 5 + r, gc = j0 + 5 + cc;
                float v = 0.f;
                if (gr < HW && gc < HW)
                    v = g_h2[(b * CMID + ci0 + ci) * HW2 + gr * HW + gc];
                sIn[ci][r][cc] = v;
            }
            for (int e = tid; e < CIC * 9 * CMID; e += 256) {
                int co = e & 63;
                int rc = e >> 6;
                int ci = rc / 9, uv = rc % 9;
                int coglob = coit * 64 + co;
                sW[ci][uv][co] = (coglob < C3)
                    ? g_W3t[((ci0 + ci) * 9 + uv) * C3 + coglob] : 0.f;
            }
            __syncthreads();

#pragma unroll 1
            for (int ci = 0; ci < CIC; ci++) {
#pragma unroll
                for (int u = 0; u < 3; u++) {
                    const float4 xa = *(const float4*)&sIn[ci][sy + u][px0];
                    const float2 xb = *(const float2*)&sIn[ci][sy + u][px0 + 4];
                    u64 xp[6];
                    xp[0] = packdup(xa.x); xp[1] = packdup(xa.y);
                    xp[2] = packdup(xa.z); xp[3] = packdup(xa.w);
                    xp[4] = packdup(xb.x); xp[5] = packdup(xb.y);
#pragma unroll
                    for (int v = 0; v < 3; v++) {
                        const ulonglong2 wA = *(const ulonglong2*)&sW[ci][u * 3 + v][co0];
                        const ulonglong2 wB = *(const ulonglong2*)&sW[ci][u * 3 + v][co0 + 4];
#pragma unroll
                        for (int k = 0; k < 4; k++) {
                            u64 xk = xp[k + v];
                            fma2(acc[k][0], xk, wA.x);
                            fma2(acc[k][1], xk, wA.y);
                            fma2(acc[k][2], xk, wB.x);
                            fma2(acc[k][3], xk, wB.y);
                        }
                    }
                }
            }
        }

        int i = i0 + sy, j = j0 + px0;
        if (i < HO && j < HO) {   // j%4==0 and HO%4==0: full float4 or skip
#pragma unroll
            for (int cp = 0; cp < 4; cp++) {
                float2 p0 = unpk(acc[0][cp]), p1 = unpk(acc[1][cp]);
                float2 p2 = unpk(acc[2][cp]), p3 = unpk(acc[3][cp]);
                int c0 = cobase + 2 * cp, c1 = cobase + 2 * cp + 1;
                if (c0 < C3)
                    *(float4*)&g_w[((b * C3 + c0) * HO + i) * HO + j] =
                        make_float4(p0.x, p1.x, p2.x, p3.x);
                if (c1 < C3)
                    *(float4*)&g_w[((b * C3 + c1) * HO + i) * HO + j] =
                        make_float4(p0.y, p1.y, p2.y, p3.y);
            }
        }
    }
}

// ---------------------------------------------------------------------------
// K4: NLM contraction: y[b,i,j] = sum_{u,v} w[b,u*13+v,i,j] * x[b,i+u,j+v]
// ---------------------------------------------------------------------------
__global__ __launch_bounds__(256) void nlm_kernel(
    const float* __restrict__ x, float* __restrict__ y)
{
    __shared__ float sX[20][44];
    int b  = blockIdx.z;
    int j0 = blockIdx.x * 32;
    int i0 = blockIdx.y * 8;
    int tid = threadIdx.x;

    for (int e = tid; e < 20 * 44; e += 256) {
        int r = e / 44, cc = e % 44;
        int gr = i0 + r, gc = j0 + cc;
        sX[r][cc] = (gr < HW && gc < HW) ? x[b * HW2 + gr * HW + gc] : 0.f;
    }
    __syncthreads();

    int tx = tid & 31, ty = tid >> 5;
    int i = i0 + ty, j = j0 + tx;
    if (i < HO && j < HO) {
        float a = 0.f;
        int wbase = (b * C3) * HO2 + i * HO + j;
#pragma unroll 1
        for (int u = 0; u < KF; u++) {
#pragma unroll
            for (int v = 0; v < KF; v++) {
                int c = u * KF + v;
                a += g_w[wbase + c * HO2] * sX[ty + u][tx + v];
            }
        }
        y[b * HO2 + i * HO + j] = a;
    }
}

// ---------------------------------------------------------------------------
extern "C" void kernel_launch(void* const* d_in, const int* in_sizes, int n_in,
                              void* d_out, int out_size)
{
    const float* x  = (const float*)d_in[0];
    const float* W1 = (const float*)d_in[1];
    const float* b1 = (const float*)d_in[2];
    const float* W2 = (const float*)d_in[3];
    const float* b2 = (const float*)d_in[4];
    const float* W3 = (const float*)d_in[5];
    const float* b3 = (const float*)d_in[6];
    float* y = (float*)d_out;

    transpose_w2<<<(CMID * CMID * 9 + 255) / 256, 256>>>(W2);
    transpose_w3<<<(C3 * CMID * 9 + 255) / 256, 256>>>(W3);
    conv1_kernel<<<dim3(HW / 32, HW / 8, BATCH), 256>>>(x, W1, b1);
    conv2_kernel<<<dim3(HW / TW, HW / TH, BATCH), 256>>>(b2);
    conv3_kernel<<<dim3((HO + TW - 1) / TW, (HO + TH - 1) / TH, BATCH), 256>>>(b3);
    nlm_kernel<<<dim3((HO + 31) / 32, (HO + 7) / 8, BATCH), 256>>>(x, y);
}